// round 2
// baseline (speedup 1.0000x reference)
#include <cuda_runtime.h>
#include <cuda_bf16.h>
#include <math.h>

#define NN   50000
#define EE   800000
#define DINF 146
#define DD   128
#define GG   64
#define LL   4
#define NCLS 10
#define ET   (EE + NN)
#define BNEPS 1e-5f

// ---------------- scratch (__device__ globals; no allocs allowed) -----------
__device__ float d_h[NN * DD];     // node features (current h / residual input)
__device__ float d_m[NN * DD];     // m = h @ W
__device__ float d_agg[NN * DD];   // aggregated messages
__device__ int   d_counts[NN];     // degree incl self-loop
__device__ int   d_offs[NN + 1];   // CSR offsets
__device__ int   d_cursor[NN];
__device__ float d_dinv[NN];
__device__ int   d_ssrc[ET];       // sorted-by-dst src ids
__device__ float d_snorm[ET];      // per-edge norm
__device__ float d_colsum[DD], d_colsq[DD], d_scale[DD], d_shift[DD];
__device__ int   d_gcnt[GG], d_gstart[GG];
__device__ float d_hg[GG * DD];
__device__ int   d_is64;

// ---------------- index dtype handling --------------------------------------
__global__ void k_detect(const void* ei) {
    if (threadIdx.x == 0) {
        const long long* p = (const long long*)ei;
        int is64 = 1;
        for (int i = 0; i < 8; i++) {
            long long v = p[i];
            if (v < 0 || v >= NN) is64 = 0;   // int32 pairs look huge as int64
        }
        d_is64 = is64;
    }
}

__device__ __forceinline__ int ld_idx(const void* p, long long i, int is64) {
    return is64 ? (int)((const long long*)p)[i] : ((const int*)p)[i];
}

// ---------------- CSR build --------------------------------------------------
__global__ void k_init_csr() {
    int i = blockIdx.x * blockDim.x + threadIdx.x;
    if (i < NN) { d_counts[i] = 1; d_cursor[i] = 0; }   // self-loop
}

__global__ void k_hist(const void* ei) {
    int e = blockIdx.x * blockDim.x + threadIdx.x;
    if (e < EE) {
        int dst = ld_idx(ei, (long long)EE + e, d_is64);
        atomicAdd(&d_counts[dst], 1);
    }
}

__global__ void k_dinv() {
    int i = blockIdx.x * blockDim.x + threadIdx.x;
    if (i < NN) d_dinv[i] = rsqrtf((float)d_counts[i]);
}

__global__ void k_scan() {   // single block, 1024 threads
    __shared__ int s[1024];
    const int T = 1024;
    int t = threadIdx.x;
    const int chunk = (NN + T - 1) / T;
    int beg = t * chunk;
    int end = min(beg + chunk, NN);
    int sum = 0;
    for (int i = beg; i < end; i++) sum += d_counts[i];
    s[t] = sum;
    __syncthreads();
    for (int off = 1; off < T; off <<= 1) {
        int v = (t >= off) ? s[t - off] : 0;
        __syncthreads();
        s[t] += v;
        __syncthreads();
    }
    int run = (t == 0) ? 0 : s[t - 1];
    for (int i = beg; i < end; i++) { d_offs[i] = run; run += d_counts[i]; }
    if (t == T - 1) d_offs[NN] = run;
}

__global__ void k_scatter(const void* ei) {
    long long e = (long long)blockIdx.x * blockDim.x + threadIdx.x;
    int is64 = d_is64;
    if (e < EE) {
        int s = ld_idx(ei, e, is64);
        int d = ld_idx(ei, (long long)EE + e, is64);
        int p = d_offs[d] + atomicAdd(&d_cursor[d], 1);
        d_ssrc[p] = s;
        d_snorm[p] = d_dinv[s] * d_dinv[d];
    } else if (e < ET) {
        int i = (int)(e - EE);
        int p = d_offs[i] + atomicAdd(&d_cursor[i], 1);
        d_ssrc[p] = i;
        float di = d_dinv[i];
        d_snorm[p] = di * di;
    }
}

// ---------------- GEMM: C[M,128] = A[M,K] * B[K,128] (+bias) -----------------
// BM=64, BN=128, BK=16, 256 threads, each thread 8x4 micro-tile.
__global__ __launch_bounds__(256) void k_gemm(
    const float* __restrict__ A, const float* __restrict__ B,
    const float* __restrict__ bias, float* __restrict__ C, int M, int K)
{
    __shared__ __align__(16) float As[64][17];
    __shared__ __align__(16) float Bs[16][128];

    int t = threadIdx.x;
    int tx = t & 31;       // col group: cols tx*4 .. tx*4+3
    int ty = t >> 5;       // row group: rows ty*8 .. ty*8+7
    int r0 = blockIdx.x * 64;

    float acc[8][4];
#pragma unroll
    for (int r = 0; r < 8; r++)
#pragma unroll
        for (int c = 0; c < 4; c++) acc[r][c] = 0.f;

    for (int kk = 0; kk < K; kk += 16) {
        // load A tile [64 rows x 16 k], 4 elems per thread
#pragma unroll
        for (int i = 0; i < 4; i++) {
            int idx = t + i * 256;
            int k = idx & 15, row = idx >> 4;
            int gr = r0 + row, gk = kk + k;
            As[row][k] = (gr < M && gk < K) ? A[(long long)gr * K + gk] : 0.f;
        }
        // load B tile [16 k x 128 cols], 8 elems per thread
#pragma unroll
        for (int i = 0; i < 8; i++) {
            int idx = t + i * 256;
            int col = idx & 127, k = idx >> 7;
            int gk = kk + k;
            Bs[k][col] = (gk < K) ? B[gk * DD + col] : 0.f;
        }
        __syncthreads();
#pragma unroll
        for (int k = 0; k < 16; k++) {
            float4 b4 = reinterpret_cast<const float4*>(&Bs[k][0])[tx];
            float a[8];
#pragma unroll
            for (int r = 0; r < 8; r++) a[r] = As[ty * 8 + r][k];
#pragma unroll
            for (int r = 0; r < 8; r++) {
                acc[r][0] = fmaf(a[r], b4.x, acc[r][0]);
                acc[r][1] = fmaf(a[r], b4.y, acc[r][1]);
                acc[r][2] = fmaf(a[r], b4.z, acc[r][2]);
                acc[r][3] = fmaf(a[r], b4.w, acc[r][3]);
            }
        }
        __syncthreads();
    }

    float4 bv = make_float4(0.f, 0.f, 0.f, 0.f);
    if (bias) bv = reinterpret_cast<const float4*>(bias)[tx];
#pragma unroll
    for (int r = 0; r < 8; r++) {
        int row = r0 + ty * 8 + r;
        if (row < M) {
            float4 o;
            o.x = acc[r][0] + bv.x;
            o.y = acc[r][1] + bv.y;
            o.z = acc[r][2] + bv.z;
            o.w = acc[r][3] + bv.w;
            reinterpret_cast<float4*>(C + (long long)row * DD)[tx] = o;
        }
    }
}

// ---------------- edge aggregation: agg[n] = sum_e norm[e]*m[src[e]] + b -----
__global__ void k_aggregate(const float* __restrict__ bias) {
    int warp = (blockIdx.x * blockDim.x + threadIdx.x) >> 5;
    int lane = threadIdx.x & 31;
    if (warp >= NN) return;
    int e0 = d_offs[warp], e1 = d_offs[warp + 1];
    const float4* m4 = reinterpret_cast<const float4*>(d_m);
    float4 acc = reinterpret_cast<const float4*>(bias)[lane];

    int e = e0;
    for (; e + 4 <= e1; e += 4) {
        int   s0 = d_ssrc[e],     s1 = d_ssrc[e + 1];
        int   s2 = d_ssrc[e + 2], s3 = d_ssrc[e + 3];
        float w0 = d_snorm[e],     w1 = d_snorm[e + 1];
        float w2 = d_snorm[e + 2], w3 = d_snorm[e + 3];
        float4 v0 = m4[(long long)s0 * 32 + lane];
        float4 v1 = m4[(long long)s1 * 32 + lane];
        float4 v2 = m4[(long long)s2 * 32 + lane];
        float4 v3 = m4[(long long)s3 * 32 + lane];
        acc.x += w0 * v0.x + w1 * v1.x + w2 * v2.x + w3 * v3.x;
        acc.y += w0 * v0.y + w1 * v1.y + w2 * v2.y + w3 * v3.y;
        acc.z += w0 * v0.z + w1 * v1.z + w2 * v2.z + w3 * v3.z;
        acc.w += w0 * v0.w + w1 * v1.w + w2 * v2.w + w3 * v3.w;
    }
    for (; e < e1; e++) {
        int s = d_ssrc[e];
        float w = d_snorm[e];
        float4 v = m4[(long long)s * 32 + lane];
        acc.x += w * v.x; acc.y += w * v.y; acc.z += w * v.z; acc.w += w * v.w;
    }
    reinterpret_cast<float4*>(d_agg)[(long long)warp * 32 + lane] = acc;
}

// ---------------- batchnorm -------------------------------------------------
__global__ void k_bn_zero() {
    int j = threadIdx.x;
    if (j < DD) { d_colsum[j] = 0.f; d_colsq[j] = 0.f; }
}

__global__ void k_bn_stats() {
    int j = threadIdx.x;   // column
    float s = 0.f, q = 0.f;
    for (int r = blockIdx.x; r < NN; r += gridDim.x) {
        float v = d_agg[(long long)r * DD + j];
        s += v;
        q += v * v;
    }
    atomicAdd(&d_colsum[j], s);
    atomicAdd(&d_colsq[j], q);
}

__global__ void k_bn_scale(const float* __restrict__ gamma,
                           const float* __restrict__ beta) {
    int j = threadIdx.x;
    if (j < DD) {
        float mu = d_colsum[j] / (float)NN;
        float var = d_colsq[j] / (float)NN - mu * mu;
        float sc = gamma[j] * rsqrtf(var + BNEPS);
        d_scale[j] = sc;
        d_shift[j] = beta[j] - mu * sc;
    }
}

__global__ void k_bn_apply() {   // h = h + relu(agg*scale+shift), float4-wide
    long long i = (long long)blockIdx.x * blockDim.x + threadIdx.x;
    const long long total = (long long)NN * DD / 4;
    if (i >= total) return;
    int c4 = (int)(i & 31);   // float4 index within row
    float4 sc = reinterpret_cast<const float4*>(d_scale)[c4];
    float4 sh = reinterpret_cast<const float4*>(d_shift)[c4];
    float4 a = reinterpret_cast<const float4*>(d_agg)[i];
    float4 h = reinterpret_cast<const float4*>(d_h)[i];
    h.x += fmaxf(0.f, a.x * sc.x + sh.x);
    h.y += fmaxf(0.f, a.y * sc.y + sh.y);
    h.z += fmaxf(0.f, a.z * sc.z + sh.z);
    h.w += fmaxf(0.f, a.w * sc.w + sh.w);
    reinterpret_cast<float4*>(d_h)[i] = h;
}

// ---------------- pooling ---------------------------------------------------
__global__ void k_gzero() { if (threadIdx.x < GG) d_gcnt[threadIdx.x] = 0; }

__global__ void k_ghist(const void* batch) {
    int i = blockIdx.x * blockDim.x + threadIdx.x;
    if (i < NN) atomicAdd(&d_gcnt[ld_idx(batch, i, d_is64)], 1);
}

__global__ void k_gscan() {
    if (threadIdx.x == 0) {
        int run = 0;
        for (int g = 0; g < GG; g++) { d_gstart[g] = run; run += d_gcnt[g]; }
    }
}

__global__ void k_pool() {
    int g = blockIdx.x, j = threadIdx.x;
    int s = d_gstart[g], c = d_gcnt[g];
    float acc = 0.f;
    for (int r = 0; r < c; r++) acc += d_h[(long long)(s + r) * DD + j];
    d_hg[g * DD + j] = (c > 0) ? acc / (float)c : 0.f;
}

// ---------------- MLP readout ------------------------------------------------
__global__ void k_mlp(const float* __restrict__ W1, const float* __restrict__ b1,
                      const float* __restrict__ W2, const float* __restrict__ b2,
                      const float* __restrict__ W3, const float* __restrict__ b3,
                      float* __restrict__ out)
{
    __shared__ float hg[DD], z1[64], z2[32];
    int g = blockIdx.x, t = threadIdx.x;
    hg[t] = d_hg[g * DD + t];
    hg[64 + t] = d_hg[g * DD + 64 + t];
    __syncthreads();
    {
        float acc = b1[t];
        for (int k = 0; k < DD; k++) acc = fmaf(hg[k], W1[k * 64 + t], acc);
        z1[t] = fmaxf(0.f, acc);
    }
    __syncthreads();
    if (t < 32) {
        float acc = b2[t];
        for (int k = 0; k < 64; k++) acc = fmaf(z1[k], W2[k * 32 + t], acc);
        z2[t] = fmaxf(0.f, acc);
    }
    __syncthreads();
    if (t < NCLS) {
        float acc = b3[t];
        for (int k = 0; k < 32; k++) acc = fmaf(z2[k], W3[k * NCLS + t], acc);
        out[g * NCLS + t] = acc;
    }
}

// ---------------- launch ------------------------------------------------------
extern "C" void kernel_launch(void* const* d_in, const int* in_sizes, int n_in,
                              void* d_out, int out_size) {
    const float* x        = (const float*)d_in[0];
    const void*  ei       = d_in[1];
    const void*  batch    = d_in[2];
    const float* W_emb    = (const float*)d_in[3];
    const float* b_emb    = (const float*)d_in[4];
    const float* W_gcn    = (const float*)d_in[5];
    const float* b_gcn    = (const float*)d_in[6];
    const float* bn_gamma = (const float*)d_in[7];
    const float* bn_beta  = (const float*)d_in[8];
    const float* W_r1     = (const float*)d_in[9];
    const float* b_r1     = (const float*)d_in[10];
    const float* W_r2     = (const float*)d_in[11];
    const float* b_r2     = (const float*)d_in[12];
    const float* W_r3     = (const float*)d_in[13];
    const float* b_r3     = (const float*)d_in[14];
    float* out = (float*)d_out;

    float* p_h;   cudaGetSymbolAddress((void**)&p_h, d_h);
    float* p_m;   cudaGetSymbolAddress((void**)&p_m, d_m);

    // --- preprocessing: norm + CSR ---
    k_detect<<<1, 32>>>(ei);
    k_init_csr<<<(NN + 255) / 256, 256>>>();
    k_hist<<<(EE + 255) / 256, 256>>>(ei);
    k_dinv<<<(NN + 255) / 256, 256>>>();
    k_scan<<<1, 1024>>>();
    k_scatter<<<(ET + 255) / 256, 256>>>(ei);

    // --- embedding ---
    k_gemm<<<(NN + 63) / 64, 256>>>(x, W_emb, b_emb, p_h, NN, DINF);

    // --- GCN layers ---
    for (int l = 0; l < LL; l++) {
        k_gemm<<<(NN + 63) / 64, 256>>>(p_h, W_gcn + l * DD * DD, nullptr, p_m, NN, DD);
        k_aggregate<<<(NN * 32 + 255) / 256, 256>>>(b_gcn + l * DD);
        k_bn_zero<<<1, 128>>>();
        k_bn_stats<<<256, 128>>>();
        k_bn_scale<<<1, 128>>>(bn_gamma + l * DD, bn_beta + l * DD);
        k_bn_apply<<<(NN * 32 + 255) / 256, 256>>>();
    }

    // --- pooling ---
    k_gzero<<<1, 64>>>();
    k_ghist<<<(NN + 255) / 256, 256>>>(batch);
    k_gscan<<<1, 32>>>();
    k_pool<<<GG, 128>>>();

    // --- MLP readout ---
    k_mlp<<<GG, 64>>>(W_r1, b_r1, W_r2, b_r2, W_r3, b_r3, out);
}

// round 4
// speedup vs baseline: 1.2312x; 1.2312x over previous
#include <cuda_runtime.h>
#include <cuda_bf16.h>
#include <math.h>
#include <cstdint>

#define NN   50000
#define EE   800000
#define DINF 146
#define DD   128
#define GG   64
#define LL   4
#define NCLS 10
#define ET   (EE + NN)
#define BNEPS 1e-5f

// ---------------- scratch (__device__ globals; no allocs allowed) -----------
__device__ float d_h[NN * DD];
__device__ float d_m[NN * DD];
__device__ float d_agg[NN * DD];
__device__ int   d_counts[NN];
__device__ int   d_offs[NN + 1];
__device__ int   d_cursor[NN];
__device__ float d_dinv[NN];
__device__ int   d_ssrc[ET];
__device__ float d_snorm[ET];
__device__ float d_colsum[DD], d_colsq[DD], d_scale[DD], d_shift[DD];
__device__ int   d_gcnt[GG], d_gstart[GG];
__device__ float d_hg[GG * DD];
__device__ int   d_is64;
__device__ float d_wt[LL * DD * DD];   // transposed layer weights [l][n][k]
__device__ float d_wtp[DD * 160];      // transposed+padded emb weights [n][k<160]

// ---------------- index dtype handling --------------------------------------
__global__ void k_detect(const void* ei) {
    if (threadIdx.x == 0) {
        const long long* p = (const long long*)ei;
        int is64 = 1;
        for (int i = 0; i < 8; i++) {
            long long v = p[i];
            if (v < 0 || v >= NN) is64 = 0;
        }
        d_is64 = is64;
    }
}

__device__ __forceinline__ int ld_idx(const void* p, long long i, int is64) {
    return is64 ? (int)((const long long*)p)[i] : ((const int*)p)[i];
}

// ---------------- weight transposes ------------------------------------------
__global__ void k_transpose_emb(const float* __restrict__ W) {
    int idx = blockIdx.x * blockDim.x + threadIdx.x;
    if (idx < DD * 160) {
        int n = idx / 160, k = idx % 160;
        d_wtp[idx] = (k < DINF) ? W[k * DD + n] : 0.f;
    }
}

__global__ void k_transpose_gcn(const float* __restrict__ W) {
    int idx = blockIdx.x * blockDim.x + threadIdx.x;
    if (idx < LL * DD * DD) {
        int l = idx / (DD * DD), r = idx % (DD * DD);
        int n = r / DD, k = r % DD;
        d_wt[idx] = W[l * DD * DD + k * DD + n];
    }
}

// ---------------- CSR build --------------------------------------------------
__global__ void k_init_csr() {
    int i = blockIdx.x * blockDim.x + threadIdx.x;
    if (i < NN) { d_counts[i] = 1; d_cursor[i] = 0; }
}

__global__ void k_hist(const void* ei) {
    int e = blockIdx.x * blockDim.x + threadIdx.x;
    if (e < EE) {
        int dst = ld_idx(ei, (long long)EE + e, d_is64);
        atomicAdd(&d_counts[dst], 1);
    }
}

__global__ void k_dinv() {
    int i = blockIdx.x * blockDim.x + threadIdx.x;
    if (i < NN) d_dinv[i] = rsqrtf((float)d_counts[i]);
}

__global__ void k_scan() {
    __shared__ int s[1024];
    const int T = 1024;
    int t = threadIdx.x;
    const int chunk = (NN + T - 1) / T;
    int beg = t * chunk;
    int end = min(beg + chunk, NN);
    int sum = 0;
    for (int i = beg; i < end; i++) sum += d_counts[i];
    s[t] = sum;
    __syncthreads();
    for (int off = 1; off < T; off <<= 1) {
        int v = (t >= off) ? s[t - off] : 0;
        __syncthreads();
        s[t] += v;
        __syncthreads();
    }
    int run = (t == 0) ? 0 : s[t - 1];
    for (int i = beg; i < end; i++) { d_offs[i] = run; run += d_counts[i]; }
    if (t == T - 1) d_offs[NN] = run;
}

__global__ void k_scatter(const void* ei) {
    long long e = (long long)blockIdx.x * blockDim.x + threadIdx.x;
    int is64 = d_is64;
    if (e < EE) {
        int s = ld_idx(ei, e, is64);
        int d = ld_idx(ei, (long long)EE + e, is64);
        int p = d_offs[d] + atomicAdd(&d_cursor[d], 1);
        d_ssrc[p] = s;
        d_snorm[p] = d_dinv[s] * d_dinv[d];
    } else if (e < ET) {
        int i = (int)(e - EE);
        int p = d_offs[i] + atomicAdd(&d_cursor[i], 1);
        d_ssrc[p] = i;
        float di = d_dinv[i];
        d_snorm[p] = di * di;
    }
}

// ======================= tf32 mma.sync GEMM =================================
// C[M,128] = A[M,K] @ Bt[128,K]^T (+bias).
// CTA tile 128x128, BK=16, 8 warps (warp tile 32x64), double-buffered smem.
// Smem rows (16 floats) stored 4x4-transposed so each fragment (covering both
// k8 steps) is one aligned LDS.128, conflict-free on the compute side.

__device__ __forceinline__ float to_tf32(float x) {
    asm("cvt.rna.tf32.f32 %0, %1;" : "=f"(x) : "f"(x));
    return x;
}

__device__ __forceinline__ void mma_tf32(float* d, uint32_t a0, uint32_t a1,
                                         uint32_t a2, uint32_t a3,
                                         uint32_t b0, uint32_t b1) {
    asm volatile(
        "mma.sync.aligned.m16n8k8.row.col.f32.tf32.tf32.f32 "
        "{%0,%1,%2,%3}, {%4,%5,%6,%7}, {%8,%9}, {%0,%1,%2,%3};"
        : "+f"(d[0]), "+f"(d[1]), "+f"(d[2]), "+f"(d[3])
        : "r"(a0), "r"(a1), "r"(a2), "r"(a3), "r"(b0), "r"(b1));
}

template<bool PADK>
__global__ __launch_bounds__(256, 2) void k_gemm_mma(
    const float* __restrict__ A, int lda, int kmax, int kiters,
    const float* __restrict__ Bt, int ldb,
    const float* __restrict__ bias,
    float* __restrict__ C, int M)
{
    __shared__ __align__(16) float As[2][128 * 16];
    __shared__ __align__(16) float Bs[2][128 * 16];

    int t = threadIdx.x;
    int wid = t >> 5, lane = t & 31;
    int wm = wid & 3, wn = wid >> 2;
    int qr = lane >> 2, qc = lane & 3;
    int m0 = blockIdx.x * 128;

    float acc[2][8][4];
#pragma unroll
    for (int mi = 0; mi < 2; mi++)
#pragma unroll
        for (int ni = 0; ni < 8; ni++)
#pragma unroll
            for (int j = 0; j < 4; j++) acc[mi][ni][j] = 0.f;

    float ra[2][4], rb[2][4];

    // ---- stage first tile into registers ----
    auto load_tile = [&](int kk) {
#pragma unroll
        for (int i = 0; i < 2; i++) {
            int slot = t + i * 256;
            int r = slot >> 2, c = slot & 3;
            int grow = m0 + r;
            if (PADK) {
#pragma unroll
                for (int d = 0; d < 4; d++) {
                    int k = kk + c * 4 + d;
                    ra[i][d] = (grow < M && k < kmax)
                             ? A[(size_t)grow * lda + k] : 0.f;
                }
            } else {
                float4 v = make_float4(0.f, 0.f, 0.f, 0.f);
                if (grow < M)
                    v = *reinterpret_cast<const float4*>(
                        A + (size_t)grow * lda + kk + c * 4);
                ra[i][0] = v.x; ra[i][1] = v.y; ra[i][2] = v.z; ra[i][3] = v.w;
            }
            float4 w = *reinterpret_cast<const float4*>(
                Bt + (size_t)r * ldb + kk + c * 4);
            rb[i][0] = w.x; rb[i][1] = w.y; rb[i][2] = w.z; rb[i][3] = w.w;
        }
    };

    load_tile(0);

    int buf = 0;
    for (int it = 0; it < kiters; it++) {
        // ---- store staged tile (tf32-rounded, 4x4-transposed rows) ----
#pragma unroll
        for (int i = 0; i < 2; i++) {
            int slot = t + i * 256;
            int r = slot >> 2, c = slot & 3;
#pragma unroll
            for (int d = 0; d < 4; d++) {
                As[buf][r * 16 + d * 4 + c] = to_tf32(ra[i][d]);
                Bs[buf][r * 16 + d * 4 + c] = to_tf32(rb[i][d]);
            }
        }
        __syncthreads();

        if (it + 1 < kiters) load_tile((it + 1) * 16);

        // ---- compute ----
        const uint4* As4 = reinterpret_cast<const uint4*>(As[buf]);
        const uint4* Bs4 = reinterpret_cast<const uint4*>(Bs[buf]);

        uint4 af[2][2];
#pragma unroll
        for (int mi = 0; mi < 2; mi++)
#pragma unroll
            for (int h = 0; h < 2; h++) {
                int row = wm * 32 + mi * 16 + h * 8 + qr;
                af[mi][h] = As4[row * 4 + qc];
            }
#pragma unroll
        for (int ni = 0; ni < 8; ni++) {
            int row = wn * 64 + ni * 8 + qr;
            uint4 bf = Bs4[row * 4 + qc];
#pragma unroll
            for (int mi = 0; mi < 2; mi++) {
                // k-step 0: k = qc, qc+4
                mma_tf32(acc[mi][ni], af[mi][0].x, af[mi][1].x,
                         af[mi][0].y, af[mi][1].y, bf.x, bf.y);
                // k-step 1: k = qc+8, qc+12
                mma_tf32(acc[mi][ni], af[mi][0].z, af[mi][1].z,
                         af[mi][0].w, af[mi][1].w, bf.z, bf.w);
            }
        }
        __syncthreads();
        buf ^= 1;
    }

    // ---- epilogue ----
#pragma unroll
    for (int mi = 0; mi < 2; mi++) {
#pragma unroll
        for (int ni = 0; ni < 8; ni++) {
            int col = wn * 64 + ni * 8 + qc * 2;
            float b0 = 0.f, b1 = 0.f;
            if (bias) { b0 = bias[col]; b1 = bias[col + 1]; }
            int r0 = m0 + wm * 32 + mi * 16 + qr;
            int r1 = r0 + 8;
            if (r0 < M) {
                float2 o = make_float2(acc[mi][ni][0] + b0, acc[mi][ni][1] + b1);
                *reinterpret_cast<float2*>(C + (size_t)r0 * DD + col) = o;
            }
            if (r1 < M) {
                float2 o = make_float2(acc[mi][ni][2] + b0, acc[mi][ni][3] + b1);
                *reinterpret_cast<float2*>(C + (size_t)r1 * DD + col) = o;
            }
        }
    }
}

// ---------------- edge aggregation -------------------------------------------
__global__ void k_aggregate(const float* __restrict__ bias) {
    int warp = (blockIdx.x * blockDim.x + threadIdx.x) >> 5;
    int lane = threadIdx.x & 31;
    if (warp >= NN) return;
    int e0 = d_offs[warp], e1 = d_offs[warp + 1];
    const float4* m4 = reinterpret_cast<const float4*>(d_m);
    float4 acc = reinterpret_cast<const float4*>(bias)[lane];

    int e = e0;
    for (; e + 4 <= e1; e += 4) {
        int   s0 = d_ssrc[e],     s1 = d_ssrc[e + 1];
        int   s2 = d_ssrc[e + 2], s3 = d_ssrc[e + 3];
        float w0 = d_snorm[e],     w1 = d_snorm[e + 1];
        float w2 = d_snorm[e + 2], w3 = d_snorm[e + 3];
        float4 v0 = m4[(long long)s0 * 32 + lane];
        float4 v1 = m4[(long long)s1 * 32 + lane];
        float4 v2 = m4[(long long)s2 * 32 + lane];
        float4 v3 = m4[(long long)s3 * 32 + lane];
        acc.x += w0 * v0.x + w1 * v1.x + w2 * v2.x + w3 * v3.x;
        acc.y += w0 * v0.y + w1 * v1.y + w2 * v2.y + w3 * v3.y;
        acc.z += w0 * v0.z + w1 * v1.z + w2 * v2.z + w3 * v3.z;
        acc.w += w0 * v0.w + w1 * v1.w + w2 * v2.w + w3 * v3.w;
    }
    for (; e < e1; e++) {
        int s = d_ssrc[e];
        float w = d_snorm[e];
        float4 v = m4[(long long)s * 32 + lane];
        acc.x += w * v.x; acc.y += w * v.y; acc.z += w * v.z; acc.w += w * v.w;
    }
    reinterpret_cast<float4*>(d_agg)[(long long)warp * 32 + lane] = acc;
}

// ---------------- batchnorm ---------------------------------------------------
__global__ void k_bn_zero() {
    int j = threadIdx.x;
    if (j < DD) { d_colsum[j] = 0.f; d_colsq[j] = 0.f; }
}

__global__ void k_bn_stats() {
    int j = threadIdx.x;
    float s = 0.f, q = 0.f;
    for (int r = blockIdx.x; r < NN; r += gridDim.x) {
        float v = d_agg[(long long)r * DD + j];
        s += v;
        q += v * v;
    }
    atomicAdd(&d_colsum[j], s);
    atomicAdd(&d_colsq[j], q);
}

__global__ void k_bn_scale(const float* __restrict__ gamma,
                           const float* __restrict__ beta) {
    int j = threadIdx.x;
    if (j < DD) {
        float mu = d_colsum[j] / (float)NN;
        float var = d_colsq[j] / (float)NN - mu * mu;
        float sc = gamma[j] * rsqrtf(var + BNEPS);
        d_scale[j] = sc;
        d_shift[j] = beta[j] - mu * sc;
    }
}

__global__ void k_bn_apply() {
    long long i = (long long)blockIdx.x * blockDim.x + threadIdx.x;
    const long long total = (long long)NN * DD / 4;
    if (i >= total) return;
    int c4 = (int)(i & 31);
    float4 sc = reinterpret_cast<const float4*>(d_scale)[c4];
    float4 sh = reinterpret_cast<const float4*>(d_shift)[c4];
    float4 a = reinterpret_cast<const float4*>(d_agg)[i];
    float4 h = reinterpret_cast<const float4*>(d_h)[i];
    h.x += fmaxf(0.f, a.x * sc.x + sh.x);
    h.y += fmaxf(0.f, a.y * sc.y + sh.y);
    h.z += fmaxf(0.f, a.z * sc.z + sh.z);
    h.w += fmaxf(0.f, a.w * sc.w + sh.w);
    reinterpret_cast<float4*>(d_h)[i] = h;
}

// ---------------- pooling -----------------------------------------------------
__global__ void k_gzero() { if (threadIdx.x < GG) d_gcnt[threadIdx.x] = 0; }

__global__ void k_ghist(const void* batch) {
    int i = blockIdx.x * blockDim.x + threadIdx.x;
    if (i < NN) atomicAdd(&d_gcnt[ld_idx(batch, i, d_is64)], 1);
}

__global__ void k_gscan() {
    if (threadIdx.x == 0) {
        int run = 0;
        for (int g = 0; g < GG; g++) { d_gstart[g] = run; run += d_gcnt[g]; }
    }
}

__global__ void k_pool() {
    int g = blockIdx.x, j = threadIdx.x;
    int s = d_gstart[g], c = d_gcnt[g];
    float acc = 0.f;
    for (int r = 0; r < c; r++) acc += d_h[(long long)(s + r) * DD + j];
    d_hg[g * DD + j] = (c > 0) ? acc / (float)c : 0.f;
}

// ---------------- MLP readout -------------------------------------------------
__global__ void k_mlp(const float* __restrict__ W1, const float* __restrict__ b1,
                      const float* __restrict__ W2, const float* __restrict__ b2,
                      const float* __restrict__ W3, const float* __restrict__ b3,
                      float* __restrict__ out)
{
    __shared__ float hg[DD], z1[64], z2[32];
    int g = blockIdx.x, t = threadIdx.x;
    hg[t] = d_hg[g * DD + t];
    hg[64 + t] = d_hg[g * DD + 64 + t];
    __syncthreads();
    {
        float acc = b1[t];
        for (int k = 0; k < DD; k++) acc = fmaf(hg[k], W1[k * 64 + t], acc);
        z1[t] = fmaxf(0.f, acc);
    }
    __syncthreads();
    if (t < 32) {
        float acc = b2[t];
        for (int k = 0; k < 64; k++) acc = fmaf(z1[k], W2[k * 32 + t], acc);
        z2[t] = fmaxf(0.f, acc);
    }
    __syncthreads();
    if (t < NCLS) {
        float acc = b3[t];
        for (int k = 0; k < 32; k++) acc = fmaf(z2[k], W3[k * NCLS + t], acc);
        out[g * NCLS + t] = acc;
    }
}

// ---------------- launch ------------------------------------------------------
extern "C" void kernel_launch(void* const* d_in, const int* in_sizes, int n_in,
                              void* d_out, int out_size) {
    const float* x        = (const float*)d_in[0];
    const void*  ei       = d_in[1];
    const void*  batch    = d_in[2];
    const float* W_emb    = (const float*)d_in[3];
    const float* b_emb    = (const float*)d_in[4];
    const float* W_gcn    = (const float*)d_in[5];
    const float* b_gcn    = (const float*)d_in[6];
    const float* bn_gamma = (const float*)d_in[7];
    const float* bn_beta  = (const float*)d_in[8];
    const float* W_r1     = (const float*)d_in[9];
    const float* b_r1     = (const float*)d_in[10];
    const float* W_r2     = (const float*)d_in[11];
    const float* b_r2     = (const float*)d_in[12];
    const float* W_r3     = (const float*)d_in[13];
    const float* b_r3     = (const float*)d_in[14];
    float* out = (float*)d_out;

    float* p_h;   cudaGetSymbolAddress((void**)&p_h, d_h);
    float* p_m;   cudaGetSymbolAddress((void**)&p_m, d_m);
    float* p_wt;  cudaGetSymbolAddress((void**)&p_wt, d_wt);
    float* p_wtp; cudaGetSymbolAddress((void**)&p_wtp, d_wtp);

    const int NBLK = (NN + 127) / 128;   // 391

    // --- preprocessing: dtype, weight transposes, norm + CSR ---
    k_detect<<<1, 32>>>(ei);
    k_transpose_emb<<<(DD * 160 + 255) / 256, 256>>>(W_emb);
    k_transpose_gcn<<<(LL * DD * DD + 255) / 256, 256>>>(W_gcn);
    k_init_csr<<<(NN + 255) / 256, 256>>>();
    k_hist<<<(EE + 255) / 256, 256>>>(ei);
    k_dinv<<<(NN + 255) / 256, 256>>>();
    k_scan<<<1, 1024>>>();
    k_scatter<<<(ET + 255) / 256, 256>>>(ei);

    // --- embedding: h = x @ W_emb + b_emb (tf32 mma.sync) ---
    k_gemm_mma<true><<<NBLK, 256>>>(x, DINF, DINF, 10, p_wtp, 160, b_emb, p_h, NN);

    // --- GCN layers ---
    for (int l = 0; l < LL; l++) {
        k_gemm_mma<false><<<NBLK, 256>>>(p_h, DD, DD, 8, p_wt + l * DD * DD, DD,
                                         nullptr, p_m, NN);
        k_aggregate<<<(NN * 32 + 255) / 256, 256>>>(b_gcn + l * DD);
        k_bn_zero<<<1, 128>>>();
        k_bn_stats<<<256, 128>>>();
        k_bn_scale<<<1, 128>>>(bn_gamma + l * DD, bn_beta + l * DD);
        k_bn_apply<<<(NN * 32 + 255) / 256, 256>>>();
    }

    // --- pooling ---
    k_gzero<<<1, 64>>>();
    k_ghist<<<(NN + 255) / 256, 256>>>(batch);
    k_gscan<<<1, 32>>>();
    k_pool<<<GG, 128>>>();

    // --- MLP readout ---
    k_mlp<<<GG, 64>>>(W_r1, b_r1, W_r2, b_r2, W_r3, b_r3, out);
}